// round 10
// baseline (speedup 1.0000x reference)
#include <cuda_runtime.h>
#include <cuda_fp16.h>
#include <cstdint>

// Conv2d 3x3 VALID, C_in=C_out=8, 2048x2048 fp32 -> (8, 2046, 2046)
// Round 10: fp16 single-MMA-per-tap conv; small tiles for high occupancy
// (TPX=64, 128 threads, ~10 CTAs/SM) + cheap staging (float2 loads,
// cvt.rn.f16x2.f32 packed hi/lo split).

#define CIN   8
#define COUT  8
#define IH    2048
#define IW    2048
#define OHH   2046
#define OWW   2046
#define CH    (IH*IW)
#define TPX   64
#define NW    4            // warps per block
#define RPW   2            // output rows per warp
#define TR    (NW*RPW)     // 8 output rows per block
#define INR   (TR+2)       // 10 input rows staged
#define INPX  (TPX+2)      // 66
#define ROWSTRIDE (INPX*8) // 528 u32 per staged row
#define NTHREADS  (NW*32)
#define NCHUNK (TPX/16)    // 4

typedef uint32_t u32;

// (hi, lo) fp16 pair of v packed in one u32: low16 = f16(v), high16 = f16(v - f32(f16(v)))
__device__ __forceinline__ u32 pack_hi_lo(float v) {
    __half h = __float2half_rn(v);
    float lo = v - __half2float(h);
    u32 r;
    asm("cvt.rn.f16x2.f32 %0, %1, %2;" : "=r"(r) : "f"(lo), "f"(v));
    return r;
}

__device__ __forceinline__ void mma16816(float* d,
                                         u32 a0, u32 a1, u32 a2, u32 a3,
                                         u32 b0, u32 b1) {
    asm volatile(
        "mma.sync.aligned.m16n8k16.row.col.f32.f16.f16.f32 "
        "{%0,%1,%2,%3}, {%4,%5,%6,%7}, {%8,%9}, {%0,%1,%2,%3};"
        : "+f"(d[0]), "+f"(d[1]), "+f"(d[2]), "+f"(d[3])
        : "r"(a0), "r"(a1), "r"(a2), "r"(a3), "r"(b0), "r"(b1));
}

__global__ __launch_bounds__(NTHREADS, 10)
void conv3x3_mma_kernel(const float* __restrict__ x,
                        const float* __restrict__ w,
                        float* __restrict__ out) {
    // stage[row][px][s]: s = cin interleaved, (cin q, q+4) adjacent -> one
    // LDS.64 gives a thread's two A-fragment words. 32B pixel stride.
    __shared__ u32 stage[INR * ROWSTRIDE];

    const int tid  = threadIdx.x;
    const int wid  = tid >> 5;
    const int lane = tid & 31;
    const int gid  = lane >> 2;   // 0..7 : fragment row / cout
    const int q    = lane & 3;    // 0..3 : k-pair / cin selector

    int x0 = blockIdx.x * TPX; if (x0 > OWW - TPX) x0 = OWW - TPX;   // 1982 tail
    int y0 = blockIdx.y * TR;  if (y0 > OHH - TR)  y0 = OHH - TR;

    // ---- weight fragments: co = gid, cin = q (+4), B word = (w, w) ----
    u32 bw[9][2];
    #pragma unroll
    for (int i = 0; i < 9; ++i) {
        int ky = i / 3, kx = i % 3;
        #pragma unroll
        for (int h = 0; h < 2; ++h) {
            int cin = q + 4 * h;
            float wv = __ldg(&w[((gid * CIN + cin) * 3 + ky) * 3 + kx]);
            u32 wu = __half_as_ushort(__float2half_rn(wv));
            bw[i][h] = wu | (wu << 16);
        }
    }

    // ---- stage inputs: 2 pixels per item, float2 loads, f16x2 pack ----
    for (int it = tid; it < INR * (INPX / 2); it += NTHREADS) {
        int b  = it / (INPX / 2);
        int xp = it - b * (INPX / 2);
        int xl = xp * 2;
        const float* ip = x + (size_t)(y0 + b) * IW + (x0 + xl);
        u32 s0[8], s1[8];
        #pragma unroll
        for (int c = 0; c < 8; ++c) {
            float2 v = *reinterpret_cast<const float2*>(ip + (size_t)c * CH);
            int s = (c & 3) * 2 + (c >> 2);
            s0[s] = pack_hi_lo(v.x);
            s1[s] = pack_hi_lo(v.y);
        }
        u32* dst = &stage[(size_t)b * ROWSTRIDE + (size_t)xl * 8];
        reinterpret_cast<uint4*>(dst)[0] = make_uint4(s0[0], s0[1], s0[2], s0[3]);
        reinterpret_cast<uint4*>(dst)[1] = make_uint4(s0[4], s0[5], s0[6], s0[7]);
        reinterpret_cast<uint4*>(dst)[2] = make_uint4(s1[0], s1[1], s1[2], s1[3]);
        reinterpret_cast<uint4*>(dst)[3] = make_uint4(s1[4], s1[5], s1[6], s1[7]);
    }
    __syncthreads();

    // ---- compute: warp handles output rows y0+2*wid, +1 ----
    const size_t PL = (size_t)OHH * OWW;
    const int r0 = y0 + RPW * wid;

    const u32* rbase[RPW + 2];
    #pragma unroll
    for (int ir = 0; ir < RPW + 2; ++ir)
        rbase[ir] = &stage[(size_t)(RPW * wid + ir) * ROWSTRIDE + (size_t)gid * 8 + 2 * q];

    #pragma unroll 1
    for (int chunk = 0; chunk < NCHUNK; ++chunk) {
        float a0[4] = {0,0,0,0};
        float a1[4] = {0,0,0,0};
        const int co = chunk * 16 * 8;   // u32 offset of chunk base pixel

        #pragma unroll
        for (int ir = 0; ir < RPW + 2; ++ir) {   // 4 distinct input rows
            const u32* rp = rbase[ir] + co;
            uint2 lo[3], hi[3];
            #pragma unroll
            for (int kx = 0; kx < 3; ++kx) {
                lo[kx] = *reinterpret_cast<const uint2*>(rp + kx * 8);
                hi[kx] = *reinterpret_cast<const uint2*>(rp + (kx + 8) * 8);
            }
            #pragma unroll
            for (int kx = 0; kx < 3; ++kx) {
                u32 f0 = lo[kx].x, f1 = hi[kx].x, f2 = lo[kx].y, f3 = hi[kx].y;
                if (ir < 3)
                    mma16816(a0, f0, f1, f2, f3, bw[ir*3+kx][0], bw[ir*3+kx][1]);
                if (ir >= 1)
                    mma16816(a1, f0, f1, f2, f3, bw[(ir-1)*3+kx][0], bw[(ir-1)*3+kx][1]);
            }
        }

        // D: [0]=D[gid][2q] [1]=D[gid][2q+1] [2]=D[gid+8][2q] [3]=D[gid+8][2q+1]
        int pix = x0 + chunk * 16 + gid;
        float* op = out + (size_t)(2 * q) * PL + (size_t)r0 * OWW + pix;
        op[0]      = a0[0];  op[PL]     = a0[1];
        op[8]      = a0[2];  op[PL + 8] = a0[3];
        op += OWW;
        op[0]      = a1[0];  op[PL]     = a1[1];
        op[8]      = a1[2];  op[PL + 8] = a1[3];
    }
}

extern "C" void kernel_launch(void* const* d_in, const int* in_sizes, int n_in,
                              void* d_out, int out_size) {
    const float* x = (const float*)d_in[0];   // (8, 2048, 2048) fp32
    const float* w = (const float*)d_in[1];   // (8, 8, 3, 3) fp32
    float* out = (float*)d_out;               // (8, 2046, 2046) fp32

    dim3 grid((OWW + TPX - 1) / TPX,          // 32
              (OHH + TR - 1) / TR);           // 256
    conv3x3_mma_kernel<<<grid, NTHREADS>>>(x, w, out);
}

// round 11
// speedup vs baseline: 1.2058x; 1.2058x over previous
#include <cuda_runtime.h>
#include <cuda_fp16.h>
#include <cstdint>

// Conv2d 3x3 VALID, C_in=C_out=8, 2048x2048 fp32 -> (8, 2046, 2046)
// Round 11: pure-fp16 mma.sync conv with kx FOLDED INTO K:
//   K = 16 = 8 cin x 2 taps -> 4x m16n8k16 + 1x m16n8k8 per output row
//   (tap pairs: (0,0)+(0,1) | (0,2)+(1,0) | (1,1)+(1,2) | (2,0)+(2,1) | (2,2))
// Staged pixel = 16B (4 u32, word q = f16x2(cin 2q, cin 2q+1)).
// 2 output rows/warp share 4 staged rows; 24 coalesced LDS.32 feed 10 MMAs.

#define CIN   8
#define IH    2048
#define IW    2048
#define OHH   2046
#define OWW   2046
#define CH    (IH*IW)
#define TPX   128
#define NW    4
#define RPW   2
#define TR    (NW*RPW)      // 8 output rows per block
#define INR   (TR+2)        // 10 staged input rows
#define INPX  (TPX+2)       // 130
#define WPP   4             // u32 words per staged pixel
#define ROWSTRIDE (INPX*WPP)
#define NTHREADS  (NW*32)
#define NCHUNK (TPX/16)     // 8

typedef uint32_t u32;

// {high16 = f16(hv), low16 = f16(lv)}
__device__ __forceinline__ u32 f16x2_pack(float hv, float lv) {
    u32 r;
    asm("cvt.rn.f16x2.f32 %0, %1, %2;" : "=r"(r) : "f"(hv), "f"(lv));
    return r;
}

__device__ __forceinline__ void mma16(float* d,
                                      u32 a0, u32 a1, u32 a2, u32 a3,
                                      u32 b0, u32 b1) {
    asm volatile(
        "mma.sync.aligned.m16n8k16.row.col.f32.f16.f16.f32 "
        "{%0,%1,%2,%3}, {%4,%5,%6,%7}, {%8,%9}, {%0,%1,%2,%3};"
        : "+f"(d[0]), "+f"(d[1]), "+f"(d[2]), "+f"(d[3])
        : "r"(a0), "r"(a1), "r"(a2), "r"(a3), "r"(b0), "r"(b1));
}

__device__ __forceinline__ void mma8(float* d, u32 a0, u32 a1, u32 b0) {
    asm volatile(
        "mma.sync.aligned.m16n8k8.row.col.f32.f16.f16.f32 "
        "{%0,%1,%2,%3}, {%4,%5}, {%6}, {%0,%1,%2,%3};"
        : "+f"(d[0]), "+f"(d[1]), "+f"(d[2]), "+f"(d[3])
        : "r"(a0), "r"(a1), "r"(b0));
}

__global__ __launch_bounds__(NTHREADS)
void conv3x3_mma_kernel(const float* __restrict__ x,
                        const float* __restrict__ w,
                        float* __restrict__ out) {
    // stage[row][pixel][q]: word q = f16x2(cin 2q (low), cin 2q+1 (high))
    __shared__ u32 stage[INR * ROWSTRIDE];

    const int tid  = threadIdx.x;
    const int wid  = tid >> 5;
    const int lane = tid & 31;
    const int gid  = lane >> 2;   // 0..7 : M row / cout col
    const int q    = lane & 3;    // 0..3 : k-pair selector

    int x0 = blockIdx.x * TPX; if (x0 > OWW - TPX) x0 = OWW - TPX;
    int y0 = blockIdx.y * TR;  if (y0 > OHH - TR)  y0 = OHH - TR;

    // ---- weight regs: wb[t] = f16x2(w[gid][2q+1][t] hi, w[gid][2q][t] lo) ----
    u32 wb[9];
    #pragma unroll
    for (int t = 0; t < 9; ++t) {
        int ky = t / 3, kx = t % 3;
        float w0v = __ldg(&w[((gid * CIN + 2 * q)     * 3 + ky) * 3 + kx]);
        float w1v = __ldg(&w[((gid * CIN + 2 * q + 1) * 3 + ky) * 3 + kx]);
        wb[t] = f16x2_pack(w1v, w0v);
    }

    // ---- stage inputs: 2 pixels per item, float2 loads, cin-pair f16x2 ----
    for (int it = tid; it < INR * (INPX / 2); it += NTHREADS) {
        int b  = it / (INPX / 2);
        int xl = (it - b * (INPX / 2)) * 2;
        const float* ip = x + (size_t)(y0 + b) * IW + (x0 + xl);
        float2 v[8];
        #pragma unroll
        for (int c = 0; c < 8; ++c)
            v[c] = *reinterpret_cast<const float2*>(ip + (size_t)c * CH);
        u32 w0[4], w1[4];
        #pragma unroll
        for (int j = 0; j < 4; ++j) {
            w0[j] = f16x2_pack(v[2*j+1].x, v[2*j].x);
            w1[j] = f16x2_pack(v[2*j+1].y, v[2*j].y);
        }
        u32* dst = &stage[(size_t)b * ROWSTRIDE + (size_t)xl * WPP];
        reinterpret_cast<uint4*>(dst)[0] = make_uint4(w0[0], w0[1], w0[2], w0[3]);
        reinterpret_cast<uint4*>(dst)[1] = make_uint4(w1[0], w1[1], w1[2], w1[3]);
    }
    __syncthreads();

    // ---- compute: warp handles output rows y0+2*wid, +1 ----
    const size_t PL = (size_t)OHH * OWW;
    const int r0 = y0 + RPW * wid;

    const u32* rbase[RPW + 2];
    #pragma unroll
    for (int ir = 0; ir < RPW + 2; ++ir)
        rbase[ir] = &stage[(size_t)(RPW * wid + ir) * ROWSTRIDE + (size_t)gid * WPP + q];

    #pragma unroll 1
    for (int chunk = 0; chunk < NCHUNK; ++chunk) {
        const int co = chunk * 16 * WPP;
        // 24 fragment words: L[ir][kx] = pixel px+kx+gid, H = px+8+kx+gid
        u32 L[4][3], H[4][3];
        #pragma unroll
        for (int ir = 0; ir < 4; ++ir) {
            const u32* rp = rbase[ir] + co;
            #pragma unroll
            for (int kx = 0; kx < 3; ++kx) {
                L[ir][kx] = rp[kx * WPP];
                H[ir][kx] = rp[(kx + 8) * WPP];
            }
        }

        float a0[4] = {0,0,0,0};
        float a1[4] = {0,0,0,0};
        // row0 taps from staged rows 0..2; row1 from 1..3 (interleaved)
        mma16(a0, L[0][0],H[0][0], L[0][1],H[0][1], wb[0], wb[1]);
        mma16(a1, L[1][0],H[1][0], L[1][1],H[1][1], wb[0], wb[1]);
        mma16(a0, L[0][2],H[0][2], L[1][0],H[1][0], wb[2], wb[3]);
        mma16(a1, L[1][2],H[1][2], L[2][0],H[2][0], wb[2], wb[3]);
        mma16(a0, L[1][1],H[1][1], L[1][2],H[1][2], wb[4], wb[5]);
        mma16(a1, L[2][1],H[2][1], L[2][2],H[2][2], wb[4], wb[5]);
        mma16(a0, L[2][0],H[2][0], L[2][1],H[2][1], wb[6], wb[7]);
        mma16(a1, L[3][0],H[3][0], L[3][1],H[3][1], wb[6], wb[7]);
        mma8 (a0, L[2][2],H[2][2], wb[8]);
        mma8 (a1, L[3][2],H[3][2], wb[8]);

        // D: [0]=D[gid][2q] [1]=D[gid][2q+1] [2]=D[gid+8][2q] [3]=D[gid+8][2q+1]
        int pix = x0 + chunk * 16 + gid;
        float* op = out + (size_t)(2 * q) * PL + (size_t)r0 * OWW + pix;
        op[0]      = a0[0];  op[PL]     = a0[1];
        op[8]      = a0[2];  op[PL + 8] = a0[3];
        op += OWW;
        op[0]      = a1[0];  op[PL]     = a1[1];
        op[8]      = a1[2];  op[PL + 8] = a1[3];
    }
}

extern "C" void kernel_launch(void* const* d_in, const int* in_sizes, int n_in,
                              void* d_out, int out_size) {
    const float* x = (const float*)d_in[0];   // (8, 2048, 2048) fp32
    const float* w = (const float*)d_in[1];   // (8, 8, 3, 3) fp32
    float* out = (float*)d_out;               // (8, 2046, 2046) fp32

    dim3 grid((OWW + TPX - 1) / TPX,          // 16
              (OHH + TR - 1) / TR);           // 256
    conv3x3_mma_kernel<<<grid, NTHREADS>>>(x, w, out);
}

// round 12
// speedup vs baseline: 1.5768x; 1.3077x over previous
#include <cuda_runtime.h>
#include <cuda_fp16.h>
#include <cstdint>

// Conv2d 3x3 VALID, C_in=C_out=8, 2048x2048 fp32 -> (8, 2046, 2046)
// Round 12: pure-fp16 mma.sync conv (kx folded into K), R11 geometry +
// latency hiding: double-buffered per-chunk fragment loads and an
// unrolled staging loop for LDG MLP.

#define CIN   8
#define IH    2048
#define IW    2048
#define OHH   2046
#define OWW   2046
#define CH    (IH*IW)
#define TPX   128
#define NW    4
#define RPW   2
#define TR    (NW*RPW)      // 8 output rows per block
#define INR   (TR+2)        // 10 staged input rows
#define INPX  (TPX+2)       // 130
#define WPP   4             // u32 words per staged pixel
#define ROWSTRIDE (INPX*WPP)
#define NTHREADS  (NW*32)
#define NCHUNK (TPX/16)     // 8
#define NITEM  (INR*(INPX/2))   // 650 staging items

typedef uint32_t u32;

__device__ __forceinline__ u32 f16x2_pack(float hv, float lv) {
    u32 r;
    asm("cvt.rn.f16x2.f32 %0, %1, %2;" : "=r"(r) : "f"(hv), "f"(lv));
    return r;
}

__device__ __forceinline__ void mma16(float* d,
                                      u32 a0, u32 a1, u32 a2, u32 a3,
                                      u32 b0, u32 b1) {
    asm volatile(
        "mma.sync.aligned.m16n8k16.row.col.f32.f16.f16.f32 "
        "{%0,%1,%2,%3}, {%4,%5,%6,%7}, {%8,%9}, {%0,%1,%2,%3};"
        : "+f"(d[0]), "+f"(d[1]), "+f"(d[2]), "+f"(d[3])
        : "r"(a0), "r"(a1), "r"(a2), "r"(a3), "r"(b0), "r"(b1));
}

__device__ __forceinline__ void mma8(float* d, u32 a0, u32 a1, u32 b0) {
    asm volatile(
        "mma.sync.aligned.m16n8k8.row.col.f32.f16.f16.f32 "
        "{%0,%1,%2,%3}, {%4,%5}, {%6}, {%0,%1,%2,%3};"
        : "+f"(d[0]), "+f"(d[1]), "+f"(d[2]), "+f"(d[3])
        : "r"(a0), "r"(a1), "r"(b0));
}

__global__ __launch_bounds__(NTHREADS)
void conv3x3_mma_kernel(const float* __restrict__ x,
                        const float* __restrict__ w,
                        float* __restrict__ out) {
    // stage[row][pixel][q]: word q = f16x2(cin 2q (low), cin 2q+1 (high))
    __shared__ u32 stage[INR * ROWSTRIDE];

    const int tid  = threadIdx.x;
    const int wid  = tid >> 5;
    const int lane = tid & 31;
    const int gid  = lane >> 2;   // 0..7 : M row (pixel) selector
    const int q    = lane & 3;    // 0..3 : k-pair / cout-pair selector

    int x0 = blockIdx.x * TPX; if (x0 > OWW - TPX) x0 = OWW - TPX;
    int y0 = blockIdx.y * TR;  if (y0 > OHH - TR)  y0 = OHH - TR;

    // ---- weight regs: wb[t] = f16x2(w[gid][2q+1][t] hi, w[gid][2q][t] lo) ----
    u32 wb[9];
    #pragma unroll
    for (int t = 0; t < 9; ++t) {
        int ky = t / 3, kx = t % 3;
        float w0v = __ldg(&w[((gid * CIN + 2 * q)     * 3 + ky) * 3 + kx]);
        float w1v = __ldg(&w[((gid * CIN + 2 * q + 1) * 3 + ky) * 3 + kx]);
        wb[t] = f16x2_pack(w1v, w0v);
    }

    // ---- stage inputs: unrolled+predicated for LDG MLP ----
    #pragma unroll
    for (int k = 0; k < (NITEM + NTHREADS - 1) / NTHREADS; ++k) {
        int it = tid + k * NTHREADS;
        if (it < NITEM) {
            int b  = it / (INPX / 2);
            int xl = (it - b * (INPX / 2)) * 2;
            const float* ip = x + (size_t)(y0 + b) * IW + (x0 + xl);
            float2 v[8];
            #pragma unroll
            for (int c = 0; c < 8; ++c)
                v[c] = *reinterpret_cast<const float2*>(ip + (size_t)c * CH);
            u32 w0[4], w1[4];
            #pragma unroll
            for (int j = 0; j < 4; ++j) {
                w0[j] = f16x2_pack(v[2*j+1].x, v[2*j].x);
                w1[j] = f16x2_pack(v[2*j+1].y, v[2*j].y);
            }
            u32* dst = &stage[(size_t)b * ROWSTRIDE + (size_t)xl * WPP];
            reinterpret_cast<uint4*>(dst)[0] = make_uint4(w0[0], w0[1], w0[2], w0[3]);
            reinterpret_cast<uint4*>(dst)[1] = make_uint4(w1[0], w1[1], w1[2], w1[3]);
        }
    }
    __syncthreads();

    // ---- compute: warp handles output rows y0+2*wid, +1 ----
    const size_t PL = (size_t)OHH * OWW;
    const int r0 = y0 + RPW * wid;

    const u32* rbase[RPW + 2];
    #pragma unroll
    for (int ir = 0; ir < RPW + 2; ++ir)
        rbase[ir] = &stage[(size_t)(RPW * wid + ir) * ROWSTRIDE + (size_t)gid * WPP + q];

    // double-buffered fragments
    u32 L[2][4][3], H[2][4][3];

    #pragma unroll
    for (int ir = 0; ir < 4; ++ir) {
        const u32* rp = rbase[ir];
        #pragma unroll
        for (int kx = 0; kx < 3; ++kx) {
            L[0][ir][kx] = rp[kx * WPP];
            H[0][ir][kx] = rp[(kx + 8) * WPP];
        }
    }

    #pragma unroll
    for (int chunk = 0; chunk < NCHUNK; ++chunk) {
        const int cur = chunk & 1, nxt = cur ^ 1;

        // prefetch next chunk's fragments (hidden under this chunk's MMAs)
        if (chunk + 1 < NCHUNK) {
            const int co = (chunk + 1) * 16 * WPP;
            #pragma unroll
            for (int ir = 0; ir < 4; ++ir) {
                const u32* rp = rbase[ir] + co;
                #pragma unroll
                for (int kx = 0; kx < 3; ++kx) {
                    L[nxt][ir][kx] = rp[kx * WPP];
                    H[nxt][ir][kx] = rp[(kx + 8) * WPP];
                }
            }
        }

        float a0[4] = {0,0,0,0};
        float a1[4] = {0,0,0,0};
        #define Lc L[cur]
        #define Hc H[cur]
        mma16(a0, Lc[0][0],Hc[0][0], Lc[0][1],Hc[0][1], wb[0], wb[1]);
        mma16(a1, Lc[1][0],Hc[1][0], Lc[1][1],Hc[1][1], wb[0], wb[1]);
        mma16(a0, Lc[0][2],Hc[0][2], Lc[1][0],Hc[1][0], wb[2], wb[3]);
        mma16(a1, Lc[1][2],Hc[1][2], Lc[2][0],Hc[2][0], wb[2], wb[3]);
        mma16(a0, Lc[1][1],Hc[1][1], Lc[1][2],Hc[1][2], wb[4], wb[5]);
        mma16(a1, Lc[2][1],Hc[2][1], Lc[2][2],Hc[2][2], wb[4], wb[5]);
        mma16(a0, Lc[2][0],Hc[2][0], Lc[2][1],Hc[2][1], wb[6], wb[7]);
        mma16(a1, Lc[3][0],Hc[3][0], Lc[3][1],Hc[3][1], wb[6], wb[7]);
        mma8 (a0, Lc[2][2],Hc[2][2], wb[8]);
        mma8 (a1, Lc[3][2],Hc[3][2], wb[8]);
        #undef Lc
        #undef Hc

        // D: [0]=D[gid][2q] [1]=D[gid][2q+1] [2]=D[gid+8][2q] [3]=D[gid+8][2q+1]
        int pix = x0 + chunk * 16 + gid;
        float* op = out + (size_t)(2 * q) * PL + (size_t)r0 * OWW + pix;
        op[0]      = a0[0];  op[PL]     = a0[1];
        op[8]      = a0[2];  op[PL + 8] = a0[3];
        op += OWW;
        op[0]      = a1[0];  op[PL]     = a1[1];
        op[8]      = a1[2];  op[PL + 8] = a1[3];
    }
}

extern "C" void kernel_launch(void* const* d_in, const int* in_sizes, int n_in,
                              void* d_out, int out_size) {
    const float* x = (const float*)d_in[0];   // (8, 2048, 2048) fp32
    const float* w = (const float*)d_in[1];   // (8, 8, 3, 3) fp32
    float* out = (float*)d_out;               // (8, 2046, 2046) fp32

    dim3 grid((OWW + TPX - 1) / TPX,          // 16
              (OHH + TR - 1) / TR);           // 256
    conv3x3_mma_kernel<<<grid, NTHREADS>>>(x, w, out);
}